// round 4
// baseline (speedup 1.0000x reference)
#include <cuda_runtime.h>
#include <cuda_bf16.h>
#include <mma.h>
#include <math.h>
#include <cstdint>

using namespace nvcuda;

#define NTOK 4096
#define DDIM 1024
#define HDIM 4096
#define ODIM 1024
#define NEXP 8
#define NPAIR 8192
#define QMAX 16256.f   // 127*128
#define CLD 132

// ---- GEMM1 (int8): CTA 128x128, 8 warps (64x32 each), BK=32, 1 CTA/SM ----
#define G1_ALD 48
#define G1_BLD 144
#define G1_ASTG (128 * G1_ALD)                  // 6144 B
#define G1_BSTG (32 * G1_BLD)                   // 4608 B
#define G1_OFF_A1 0
#define G1_OFF_A0 (2 * G1_ASTG)
#define G1_OFF_B1 (4 * G1_ASTG)
#define G1_OFF_B0 (4 * G1_ASTG + 2 * G1_BSTG)
#define G1_SMEM 67584                            // >= max(43008, 128*132*4)

// ---- GEMM2 (bf16 x3): CTA 128x128, 4 warps (64x64 each), BK=32, 2 CTA/SM ----
#define G2_ALD 40
#define G2_BLD 136
#define G2_ASTG (128 * G2_ALD * 2)              // 10240 B per stage per term
#define G2_BSTG (32 * G2_BLD * 2)               // 8704 B
#define G2_OFF_AH 0
#define G2_OFF_AL (2 * G2_ASTG)
#define G2_OFF_BH (4 * G2_ASTG)
#define G2_OFF_BL (4 * G2_ASTG + 2 * G2_BSTG)
#define G2_SMEM (4 * G2_ASTG + 4 * G2_BSTG)     // 75776 (C tile 67584 fits)

#define SMEM_ROUTER (16 * DDIM * 4)
#define G1_GRID 152
#define G2_GRID 304
#define MAXMT 80

__device__ __forceinline__ uint32_t smem_u32(const void* p) {
    uint32_t a;
    asm("{ .reg .u64 t; cvta.to.shared.u64 t, %1; cvt.u32.u64 %0, t; }" : "=r"(a) : "l"(p));
    return a;
}
#define CP_ASYNC16(dst, src, sz) \
    asm volatile("cp.async.cg.shared.global [%0], [%1], 16, %2;" \
                 :: "r"(dst), "l"(src), "r"(sz))
#define CP_COMMIT() asm volatile("cp.async.commit_group;")
#define CP_WAIT0()  asm volatile("cp.async.wait_group 0;")

// ---------------- scratch ----------------
__device__ int   g_cnt[NEXP];
__device__ int   g_off[NEXP];
__device__ int   g_tok[NEXP * NTOK];
__device__ float g_gate[NEXP * NTOK];
__device__ signed char g_xq1[NTOK * DDIM];
__device__ signed char g_xq0[NTOK * DDIM];
__device__ float g_sx[NTOK];
__device__ signed char g_wq1[NEXP * DDIM * HDIM];
__device__ signed char g_wq0[NEXP * DDIM * HDIM];
__device__ float g_sw[NEXP * HDIM];
__device__ __nv_bfloat16 g_hhi[(size_t)NPAIR * HDIM];
__device__ __nv_bfloat16 g_hlo[(size_t)NPAIR * HDIM];
__device__ int g_mte[MAXMT];
__device__ int g_mtm[MAXMT];
__device__ int g_njobs1, g_njobs2;
__device__ int g_jobq1, g_jobq2;

// ---------------- quantize x: per-row scale, 2x int8 ----------------
__global__ void quant_x_kernel(const float* __restrict__ x) {
    __shared__ float red[8];
    int row = blockIdx.x;
    int tid = threadIdx.x;
    const float* xr = x + (size_t)row * DDIM;
    float m = 0.f;
#pragma unroll
    for (int i = 0; i < 4; ++i) m = fmaxf(m, fabsf(xr[tid + 256 * i]));
#pragma unroll
    for (int d = 16; d > 0; d >>= 1) m = fmaxf(m, __shfl_xor_sync(0xffffffffu, m, d));
    if ((tid & 31) == 0) red[tid >> 5] = m;
    __syncthreads();
    if (tid < 8) {
        float v = red[tid];
#pragma unroll
        for (int d = 4; d > 0; d >>= 1) v = fmaxf(v, __shfl_xor_sync(0xffu, v, d));
        if (tid == 0) { red[0] = fmaxf(v, 1e-20f); g_sx[row] = red[0] / QMAX; }
    }
    __syncthreads();
    float s = red[0] / QMAX;
    float inv = 1.f / s;
#pragma unroll
    for (int i = 0; i < 4; ++i) {
        int k = tid + 256 * i;
        float v = xr[k] * inv;                // in units of s, |v| <= 16256
        int a1 = __float2int_rn(v * 0.0078125f);   // /128
        a1 = max(-127, min(127, a1));
        int a0 = __float2int_rn(v - 128.f * a1);
        a0 = max(-127, min(127, a0));
        g_xq1[(size_t)row * DDIM + k] = (signed char)a1;
        g_xq0[(size_t)row * DDIM + k] = (signed char)a0;
    }
}

// ---------------- quantize W1: per-(e,n) column scale, 2x int8 ----------------
__global__ void quant_w1_kernel(const float* __restrict__ W1) {
    int e = blockIdx.y;
    int n = blockIdx.x * 128 + threadIdx.x;
    const float* Wp = W1 + (size_t)e * DDIM * HDIM;
    float m = 1e-20f;
    for (int k = 0; k < DDIM; ++k) m = fmaxf(m, fabsf(Wp[(size_t)k * HDIM + n]));
    float s = m / QMAX;
    g_sw[e * HDIM + n] = s;
    float inv = 1.f / s;
    for (int k = 0; k < DDIM; ++k) {
        size_t idx = (size_t)e * DDIM * HDIM + (size_t)k * HDIM + n;
        float v = Wp[(size_t)k * HDIM + n] * inv;
        int a1 = __float2int_rn(v * 0.0078125f);
        a1 = max(-127, min(127, a1));
        int a0 = __float2int_rn(v - 128.f * a1);
        a0 = max(-127, min(127, a0));
        g_wq1[idx] = (signed char)a1;
        g_wq0[idx] = (signed char)a0;
    }
}

// ---------------- router: noisy top-2 ----------------
__global__ void router_kernel(const float* __restrict__ x,
                              const float* __restrict__ noise,
                              const float* __restrict__ Wg,
                              const float* __restrict__ bg,
                              const float* __restrict__ Wn,
                              const float* __restrict__ bn) {
    extern __shared__ float Ws[];  // [16][DDIM]
    int tid = threadIdx.x;
    for (int idx = tid; idx < DDIM * NEXP; idx += blockDim.x) {
        int k = idx >> 3, o = idx & 7;
        Ws[o * DDIM + k]       = Wg[idx];
        Ws[(8 + o) * DDIM + k] = Wn[idx];
    }
    __syncthreads();
    int warp = tid >> 5, lane = tid & 31;
#pragma unroll 1
    for (int it = 0; it < 2; ++it) {
        int t = blockIdx.x * 16 + warp * 2 + it;
        float acc[16];
#pragma unroll
        for (int o = 0; o < 16; ++o) acc[o] = 0.f;
        const float* xr = x + (long)t * DDIM;
        for (int j = 0; j < 32; ++j) {
            int k = lane + 32 * j;
            float xv = xr[k];
#pragma unroll
            for (int o = 0; o < 16; ++o) acc[o] += xv * Ws[o * DDIM + k];
        }
#pragma unroll
        for (int o = 0; o < 16; ++o) {
            float v = acc[o];
            v += __shfl_xor_sync(0xffffffffu, v, 16);
            v += __shfl_xor_sync(0xffffffffu, v, 8);
            v += __shfl_xor_sync(0xffffffffu, v, 4);
            v += __shfl_xor_sync(0xffffffffu, v, 2);
            v += __shfl_xor_sync(0xffffffffu, v, 1);
            acc[o] = v;
        }
        if (lane == 0) {
            float noisy[8];
#pragma unroll
            for (int o = 0; o < 8; ++o) {
                float lg = acc[o] + bg[o];
                float nl = acc[8 + o] + bn[o];
                float sp = nl > 20.f ? nl : log1pf(expf(nl));
                noisy[o] = lg + noise[(long)t * 8 + o] * sp;
            }
            int i1 = 0; float v1 = noisy[0];
#pragma unroll
            for (int o = 1; o < 8; ++o) if (noisy[o] > v1) { v1 = noisy[o]; i1 = o; }
            int i2 = 0; float v2 = -3.4e38f;
#pragma unroll
            for (int o = 0; o < 8; ++o) if (o != i1 && noisy[o] > v2) { v2 = noisy[o]; i2 = o; }
            float ex = expf(v2 - v1);
            float inv = 1.f / (1.f + ex);
            int p1 = atomicAdd(&g_cnt[i1], 1);
            g_tok[i1 * NTOK + p1]  = t;
            g_gate[i1 * NTOK + p1] = inv;
            int p2 = atomicAdd(&g_cnt[i2], 1);
            g_tok[i2 * NTOK + p2]  = t;
            g_gate[i2 * NTOK + p2] = ex * inv;
        }
    }
}

// ---------------- scan: offsets + m-tile list + job counters ----------------
__global__ void scan_kernel() {
    if (threadIdx.x == 0) {
        int s = 0, nt = 0;
#pragma unroll
        for (int e = 0; e < NEXP; ++e) {
            g_off[e] = s;
            int c = g_cnt[e];
            s += c;
            for (int m0 = 0; m0 < c; m0 += 128) { g_mte[nt] = e; g_mtm[nt] = m0; ++nt; }
        }
        g_njobs1 = nt * (HDIM / 128);
        g_njobs2 = nt * (ODIM / 128);
        g_jobq1 = 0;
        g_jobq2 = 0;
    }
}

// ---------------- GEMM1: int8 two-word, persistent ----------------
__global__ void __launch_bounds__(256, 1)
gemm1_kernel(const float* __restrict__ b1) {
    constexpr int KT = DDIM / 32;
    extern __shared__ __align__(128) char raw[];
    uint32_t sbase = smem_u32(raw);
    __shared__ int jidx;

    int tid = threadIdx.x;
    int w = tid >> 5;
    int wm = (w & 1) * 64, wn = (w >> 1) * 32;
    int njobs = g_njobs1;

    // static chunk mapping
    int arow = tid >> 1, ac = tid & 1;       // A: row, 16B chunk
    int brow = tid >> 3, bc = tid & 7;       // B: row, 16B chunk

    while (true) {
        if (tid == 0) jidx = atomicAdd(&g_jobq1, 1);
        __syncthreads();
        int j = jidx;
        if (j >= njobs) break;
        int tile = j >> 5;
        int n0 = (j & 31) * 128;
        int e = g_mte[tile], m0 = g_mtm[tile];
        int cnt = g_cnt[e], off = g_off[e];

        int apos = m0 + arow;
        bool aval = apos < cnt;
        uint32_t asz = aval ? 16u : 0u;
        int token = aval ? g_tok[e * NTOK + apos] : 0;
        const signed char* a1p = g_xq1 + (size_t)token * DDIM + ac * 16;
        const signed char* a0p = g_xq0 + (size_t)token * DDIM + ac * 16;
        uint32_t adst = sbase + arow * G1_ALD + ac * 16;
        size_t bbase = (size_t)e * DDIM * HDIM + (size_t)brow * HDIM + n0 + bc * 16;
        uint32_t bdst = sbase + G1_OFF_B1 + brow * G1_BLD + bc * 16;

        auto fill = [&](int s, int kt) {
            int ko = kt * 32;
            uint32_t sa = s * G1_ASTG, sb = s * G1_BSTG;
            CP_ASYNC16(adst + sa, a1p + ko, asz);
            CP_ASYNC16(adst + sa + G1_OFF_A0, a0p + ko, asz);
            size_t kofs = (size_t)ko * HDIM;
            CP_ASYNC16(bdst + sb, g_wq1 + bbase + kofs, 16u);
            CP_ASYNC16(bdst + sb + (G1_OFF_B0 - G1_OFF_B1), g_wq0 + bbase + kofs, 16u);
            CP_COMMIT();
        };

        wmma::fragment<wmma::accumulator, 16, 16, 16, int> accH[4][2], accM[4][2];
#pragma unroll
        for (int i = 0; i < 4; ++i)
#pragma unroll
            for (int jj = 0; jj < 2; ++jj) {
                wmma::fill_fragment(accH[i][jj], 0);
                wmma::fill_fragment(accM[i][jj], 0);
            }

        auto compute = [&](int s) {
            const signed char* A1 = (const signed char*)(raw + s * G1_ASTG);
            const signed char* A0 = (const signed char*)(raw + G1_OFF_A0 + s * G1_ASTG);
            const signed char* B1 = (const signed char*)(raw + G1_OFF_B1 + s * G1_BSTG);
            const signed char* B0 = (const signed char*)(raw + G1_OFF_B0 + s * G1_BSTG);
#pragma unroll
            for (int kk = 0; kk < 32; kk += 16) {
                wmma::fragment<wmma::matrix_a, 16, 16, 16, signed char, wmma::row_major> fa1[4], fa0[4];
                wmma::fragment<wmma::matrix_b, 16, 16, 16, signed char, wmma::row_major> fb1[2], fb0[2];
#pragma unroll
                for (int i = 0; i < 4; ++i) {
                    wmma::load_matrix_sync(fa1[i], A1 + (wm + 16 * i) * G1_ALD + kk, G1_ALD);
                    wmma::load_matrix_sync(fa0[i], A0 + (wm + 16 * i) * G1_ALD + kk, G1_ALD);
                }
#pragma unroll
                for (int jj = 0; jj < 2; ++jj) {
                    wmma::load_matrix_sync(fb1[jj], B1 + kk * G1_BLD + wn + 16 * jj, G1_BLD);
                    wmma::load_matrix_sync(fb0[jj], B0 + kk * G1_BLD + wn + 16 * jj, G1_BLD);
                }
#pragma unroll
                for (int i = 0; i < 4; ++i)
#pragma unroll
                    for (int jj = 0; jj < 2; ++jj) {
                        wmma::mma_sync(accH[i][jj], fa1[i], fb1[jj], accH[i][jj]);
                        wmma::mma_sync(accM[i][jj], fa1[i], fb0[jj], accM[i][jj]);
                        wmma::mma_sync(accM[i][jj], fa0[i], fb1[jj], accM[i][jj]);
                    }
            }
        };

        fill(0, 0);
        CP_WAIT0();
        __syncthreads();
#pragma unroll 1
        for (int kt = 0; kt < KT; ++kt) {
            int s = kt & 1;
            if (kt + 1 < KT) fill(s ^ 1, kt + 1);
            compute(s);
            if (kt + 1 < KT) {
                CP_WAIT0();
                __syncthreads();
            }
        }

        __syncthreads();
        float* sC = (float*)raw;
#pragma unroll
        for (int i = 0; i < 4; ++i)
#pragma unroll
            for (int jj = 0; jj < 2; ++jj) {
                wmma::fragment<wmma::accumulator, 16, 16, 16, float> f;
#pragma unroll
                for (int t2 = 0; t2 < f.num_elements; ++t2)
                    f.x[t2] = 16384.f * (float)accH[i][jj].x[t2] + 128.f * (float)accM[i][jj].x[t2];
                wmma::store_matrix_sync(sC + (wm + 16 * i) * CLD + wn + 16 * jj, f, CLD,
                                        wmma::mem_row_major);
            }
        __syncthreads();

#pragma unroll 1
        for (int q = tid; q < 128 * 32; q += 256) {
            int r = q >> 5;
            int c = (q & 31) * 4;
            int pos = m0 + r;
            if (pos >= cnt) continue;
            int tokr = g_tok[e * NTOK + pos];
            float sx = g_sx[tokr];
            int nb = n0 + c;
            size_t ob = (size_t)(off + pos) * HDIM + nb;
#pragma unroll
            for (int u = 0; u < 4; u += 2) {
                float v0 = sC[r * CLD + c + u]     * (sx * g_sw[e * HDIM + nb + u])     + b1[e * HDIM + nb + u];
                float v1 = sC[r * CLD + c + u + 1] * (sx * g_sw[e * HDIM + nb + u + 1]) + b1[e * HDIM + nb + u + 1];
                v0 = fmaxf(v0, 0.f);
                v1 = fmaxf(v1, 0.f);
                __nv_bfloat16 h0 = __float2bfloat16(v0), h1 = __float2bfloat16(v1);
                *(__nv_bfloat162*)(g_hhi + ob + u) = __halves2bfloat162(h0, h1);
                *(__nv_bfloat162*)(g_hlo + ob + u) =
                    __halves2bfloat162(__float2bfloat16(v0 - __bfloat162float(h0)),
                                       __float2bfloat16(v1 - __bfloat162float(h1)));
            }
        }
        __syncthreads();
    }
}

// ---------------- GEMM2: bf16x3, persistent, in-kernel W2 convert ----------------
__global__ void __launch_bounds__(128, 2)
gemm2_kernel(const float* __restrict__ W2, const float* __restrict__ b2,
             float* __restrict__ out) {
    constexpr int KT = HDIM / 32;
    extern __shared__ __align__(128) char raw[];
    uint32_t sbase = smem_u32(raw);
    __shared__ int jidx;

    int tid = threadIdx.x;
    int w = tid >> 5;
    int wm = (w & 1) * 64, wn = (w >> 1) * 64;
    int njobs = g_njobs2;

    int brow = tid >> 5, bc4 = tid & 31;   // B: base row (of 4 groups x8), float4 col

    while (true) {
        if (tid == 0) jidx = atomicAdd(&g_jobq2, 1);
        __syncthreads();
        int j = jidx;
        if (j >= njobs) break;
        int tile = j >> 3;
        int n0 = (j & 7) * 128;
        int e = g_mte[tile], m0 = g_mtm[tile];
        int cnt = g_cnt[e], off = g_off[e];

        int arow = tid;
        int apos = m0 + arow;
        bool aval = apos < cnt;
        uint32_t asz = aval ? 16u : 0u;
        size_t abase = (size_t)(off + (aval ? apos : 0)) * HDIM;
        uint32_t adst = sbase + arow * (G2_ALD * 2);
        const float* Wp = W2 + (size_t)e * HDIM * ODIM;

        auto fillA = [&](int s, int kt) {
            int ko = kt * 32;
            uint32_t sa = s * G2_ASTG;
#pragma unroll
            for (int c = 0; c < 4; ++c) {
                CP_ASYNC16(adst + sa + c * 16, (const char*)(g_hhi + abase + ko + c * 8), asz);
                CP_ASYNC16(adst + sa + G2_OFF_AL + c * 16, (const char*)(g_hlo + abase + ko + c * 8), asz);
            }
            CP_COMMIT();
        };

        float4 breg[8];
        auto ldgB = [&](int kt) {
            int ko = kt * 32;
#pragma unroll
            for (int i = 0; i < 8; ++i)
                breg[i] = *(const float4*)(Wp + (size_t)(ko + brow + 4 * i) * ODIM + n0 + bc4 * 4);
        };
        auto stsB = [&](int s) {
            char* bh = raw + G2_OFF_BH + s * G2_BSTG;
            char* bl = raw + G2_OFF_BL + s * G2_BSTG;
#pragma unroll
            for (int i = 0; i < 8; ++i) {
                float4 v = breg[i];
                __nv_bfloat16 h0 = __float2bfloat16(v.x), h1 = __float2bfloat16(v.y);
                __nv_bfloat16 h2 = __float2bfloat16(v.z), h3 = __float2bfloat16(v.w);
                __nv_bfloat162 ph0 = __halves2bfloat162(h0, h1);
                __nv_bfloat162 ph1 = __halves2bfloat162(h2, h3);
                __nv_bfloat162 pl0 = __halves2bfloat162(__float2bfloat16(v.x - __bfloat162float(h0)),
                                                        __float2bfloat16(v.y - __bfloat162float(h1)));
                __nv_bfloat162 pl1 = __halves2bfloat162(__float2bfloat16(v.z - __bfloat162float(h2)),
                                                        __float2bfloat16(v.w - __bfloat162float(h3)));
                uint32_t o = (brow + 4 * i) * (G2_BLD * 2) + bc4 * 8;
                uint2 hh, ll;
                hh.x = *(uint32_t*)&ph0; hh.y = *(uint32_t*)&ph1;
                ll.x = *(uint32_t*)&pl0; ll.y = *(uint32_t*)&pl1;
                *(uint2*)(bh + o) = hh;
                *(uint2*)(bl + o) = ll;
            }
        };

        wmma::fragment<wmma::accumulator, 16, 16, 16, float> acc[4][4];
#pragma unroll
        for (int i = 0; i < 4; ++i)
#pragma unroll
            for (int jj = 0; jj < 4; ++jj) wmma::fill_fragment(acc[i][jj], 0.f);

        auto compute = [&](int s) {
            const __nv_bfloat16* Ah = (const __nv_bfloat16*)(raw + s * G2_ASTG);
            const __nv_bfloat16* Al = (const __nv_bfloat16*)(raw + G2_OFF_AL + s * G2_ASTG);
            const __nv_bfloat16* Bh = (const __nv_bfloat16*)(raw + G2_OFF_BH + s * G2_BSTG);
            const __nv_bfloat16* Bl = (const __nv_bfloat16*)(raw + G2_OFF_BL + s * G2_BSTG);
#pragma unroll
            for (int kk = 0; kk < 32; kk += 16) {
                wmma::fragment<wmma::matrix_a, 16, 16, 16, __nv_bfloat16, wmma::row_major> fa[4];
                wmma::fragment<wmma::matrix_b, 16, 16, 16, __nv_bfloat16, wmma::row_major> fbh[4], fbl[4];
#pragma unroll
                for (int i = 0; i < 4; ++i)
                    wmma::load_matrix_sync(fa[i], Ah + (wm + 16 * i) * G2_ALD + kk, G2_ALD);
#pragma unroll
                for (int jj = 0; jj < 4; ++jj) {
                    wmma::load_matrix_sync(fbh[jj], Bh + kk * G2_BLD + wn + 16 * jj, G2_BLD);
                    wmma::load_matrix_sync(fbl[jj], Bl + kk * G2_BLD + wn + 16 * jj, G2_BLD);
                }
#pragma unroll
                for (int i = 0; i < 4; ++i)
#pragma unroll
                    for (int jj = 0; jj < 4; ++jj) {
                        wmma::mma_sync(acc[i][jj], fa[i], fbh[jj], acc[i][jj]);
                        wmma::mma_sync(acc[i][jj], fa[i], fbl[jj], acc[i][jj]);
                    }
#pragma unroll
                for (int i = 0; i < 4; ++i)
                    wmma::load_matrix_sync(fa[i], Al + (wm + 16 * i) * G2_ALD + kk, G2_ALD);
#pragma unroll
                for (int i = 0; i < 4; ++i)
#pragma unroll
                    for (int jj = 0; jj < 4; ++jj)
                        wmma::mma_sync(acc[i][jj], fa[i], fbh[jj], acc[i][jj]);
            }
        };

        fillA(0, 0);
        ldgB(0);
        stsB(0);
        CP_WAIT0();
        __syncthreads();
#pragma unroll 1
        for (int kt = 0; kt < KT; ++kt) {
            int s = kt & 1;
            if (kt + 1 < KT) { fillA(s ^ 1, kt + 1); ldgB(kt + 1); }
            compute(s);
            if (kt + 1 < KT) {
                stsB(s ^ 1);
                CP_WAIT0();
                __syncthreads();
            }
        }

        __syncthreads();
        float* sC = (float*)raw;
#pragma unroll
        for (int i = 0; i < 4; ++i)
#pragma unroll
            for (int jj = 0; jj < 4; ++jj)
                wmma::store_matrix_sync(sC + (wm + 16 * i) * CLD + wn + 16 * jj, acc[i][jj], CLD,
                                        wmma::mem_row_major);
        __syncthreads();

#pragma unroll 1
        for (int q = tid; q < 128 * 32; q += 128) {
            int r = q >> 5;
            int c = (q & 31) * 4;
            int pos = m0 + r;
            if (pos >= cnt) continue;
            float gate = g_gate[e * NTOK + pos];
            int token  = g_tok[e * NTOK + pos];
            int nb = n0 + c;
            float* op = out + (size_t)token * ODIM + nb;
#pragma unroll
            for (int u = 0; u < 4; ++u) {
                float v = sC[r * CLD + c + u] + b2[e * ODIM + nb + u];
                atomicAdd(op + u, v * gate);
            }
        }
        __syncthreads();
    }
}

// ---------------- launch ----------------
extern "C" void kernel_launch(void* const* d_in, const int* in_sizes, int n_in,
                              void* d_out, int out_size) {
    const float* x     = (const float*)d_in[0];
    const float* noise = (const float*)d_in[1];
    const float* Wg    = (const float*)d_in[2];
    const float* bg    = (const float*)d_in[3];
    const float* Wn    = (const float*)d_in[4];
    const float* bn    = (const float*)d_in[5];
    const float* W1    = (const float*)d_in[6];
    const float* b1    = (const float*)d_in[7];
    const float* W2    = (const float*)d_in[8];
    const float* b2    = (const float*)d_in[9];
    (void)in_sizes; (void)n_in;

    void* cnt_ptr;
    cudaGetSymbolAddress(&cnt_ptr, g_cnt);

    cudaFuncSetAttribute(router_kernel, cudaFuncAttributeMaxDynamicSharedMemorySize, SMEM_ROUTER);
    cudaFuncSetAttribute(gemm1_kernel, cudaFuncAttributeMaxDynamicSharedMemorySize, G1_SMEM);
    cudaFuncSetAttribute(gemm2_kernel, cudaFuncAttributeMaxDynamicSharedMemorySize, G2_SMEM);

    cudaMemsetAsync(cnt_ptr, 0, NEXP * sizeof(int));
    cudaMemsetAsync(d_out, 0, (size_t)out_size * sizeof(float));

    quant_x_kernel<<<NTOK, 256>>>(x);
    quant_w1_kernel<<<dim3(HDIM / 128, NEXP), 128>>>(W1);
    router_kernel<<<NTOK / 16, 256, SMEM_ROUTER>>>(x, noise, Wg, bg, Wn, bn);
    scan_kernel<<<1, 32>>>();

    gemm1_kernel<<<G1_GRID, 256, G1_SMEM>>>(b1);
    gemm2_kernel<<<G2_GRID, 128, G2_SMEM>>>(W2, b2, (float*)d_out);
}

// round 5
// speedup vs baseline: 4.1905x; 4.1905x over previous
#include <cuda_runtime.h>
#include <cuda_fp16.h>
#include <mma.h>
#include <math.h>
#include <cstdint>

using namespace nvcuda;

#define NTOK 4096
#define DDIM 1024
#define HDIM 4096
#define ODIM 1024
#define NEXP 8
#define NPAIR 8192

#define BM 128
#define BN 256
#define BK 64
#define ALD 72      // A smem row stride (halfs)
#define BLD 264     // B smem row stride (halfs)
#define CLD 264     // C smem row stride (floats)

#define A_STAGE (BM * ALD * 2)            // 18432 B
#define B_STAGE (BK * BLD * 2)            // 33792 B
#define OFF_A  0
#define OFF_BH (2 * A_STAGE)              // 36864
#define OFF_BL (OFF_BH + 2 * B_STAGE)     // 104448
#define SMEM_GEMM (OFF_BL + 2 * B_STAGE)  // 172032
#define SMEM_ROUTER (16 * DDIM * 4)

__device__ __forceinline__ uint32_t smem_u32(const void* p) {
    uint32_t a;
    asm("{ .reg .u64 t; cvta.to.shared.u64 t, %1; cvt.u32.u64 %0, t; }" : "=r"(a) : "l"(p));
    return a;
}
#define CP_ASYNC16(dst, src, sz) \
    asm volatile("cp.async.cg.shared.global [%0], [%1], 16, %2;" \
                 :: "r"(dst), "l"(src), "r"(sz))
#define CP_COMMIT() asm volatile("cp.async.commit_group;")
#define CP_WAIT0()  asm volatile("cp.async.wait_group 0;")

// ---------------- scratch (device globals) ----------------
__device__ int   g_cnt[NEXP];
__device__ int   g_tok[NEXP * NTOK];
__device__ float g_gate[NEXP * NTOK];
__device__ __half g_xh[NTOK * DDIM];                 // fp16(x)
__device__ __half g_w1h[NEXP * DDIM * HDIM];         // fp16 hi
__device__ __half g_w1l[NEXP * DDIM * HDIM];         // fp16 lo (residual)
__device__ __half g_w2h[NEXP * HDIM * ODIM];
__device__ __half g_w2l[NEXP * HDIM * ODIM];
__device__ __half g_h[(size_t)NPAIR * HDIM];         // fp16(h)

// ---------------- x: fp32 -> fp16 convert ----------------
__global__ void conv_x_kernel(const float4* __restrict__ src) {
    int i = blockIdx.x * blockDim.x + threadIdx.x;
    if (i >= NTOK * DDIM / 4) return;
    float4 v = src[i];
    __half2* dst = (__half2*)g_xh;
    dst[2 * i]     = __halves2half2(__float2half_rn(v.x), __float2half_rn(v.y));
    dst[2 * i + 1] = __halves2half2(__float2half_rn(v.z), __float2half_rn(v.w));
}

// ---------------- W1 + W2: fp32 -> fp16 hi/lo split (one kernel) ----------------
__global__ void split_w_kernel(const float4* __restrict__ W1,
                               const float4* __restrict__ W2) {
    const int n4 = NEXP * DDIM * HDIM / 4;
    int i = blockIdx.x * blockDim.x + threadIdx.x;
    if (i >= 2 * n4) return;
    bool second = i >= n4;
    int j = second ? i - n4 : i;
    float4 v = second ? W2[j] : W1[j];
    __half h0 = __float2half_rn(v.x);
    __half h1 = __float2half_rn(v.y);
    __half h2 = __float2half_rn(v.z);
    __half h3 = __float2half_rn(v.w);
    __half2* hi = (__half2*)(second ? g_w2h : g_w1h);
    __half2* lo = (__half2*)(second ? g_w2l : g_w1l);
    hi[2 * j]     = __halves2half2(h0, h1);
    hi[2 * j + 1] = __halves2half2(h2, h3);
    lo[2 * j]     = __halves2half2(__float2half_rn(v.x - __half2float(h0)),
                                   __float2half_rn(v.y - __half2float(h1)));
    lo[2 * j + 1] = __halves2half2(__float2half_rn(v.z - __half2float(h2)),
                                   __float2half_rn(v.w - __half2float(h3)));
}

// ---------------- router: noisy top-2 ----------------
__global__ void router_kernel(const float* __restrict__ x,
                              const float* __restrict__ noise,
                              const float* __restrict__ Wg,
                              const float* __restrict__ bg,
                              const float* __restrict__ Wn,
                              const float* __restrict__ bn) {
    extern __shared__ float Ws[];  // [16][DDIM]
    int tid = threadIdx.x;
    for (int idx = tid; idx < DDIM * NEXP; idx += blockDim.x) {
        int k = idx >> 3, o = idx & 7;
        Ws[o * DDIM + k]       = Wg[idx];
        Ws[(8 + o) * DDIM + k] = Wn[idx];
    }
    __syncthreads();
    int warp = tid >> 5, lane = tid & 31;
    int t = blockIdx.x * 8 + warp;
    float acc[16];
#pragma unroll
    for (int o = 0; o < 16; ++o) acc[o] = 0.f;
    const float* xr = x + (long)t * DDIM;
    for (int j = 0; j < 32; ++j) {
        int k = lane + 32 * j;
        float xv = xr[k];
#pragma unroll
        for (int o = 0; o < 16; ++o) acc[o] += xv * Ws[o * DDIM + k];
    }
#pragma unroll
    for (int o = 0; o < 16; ++o) {
        float v = acc[o];
        v += __shfl_xor_sync(0xffffffffu, v, 16);
        v += __shfl_xor_sync(0xffffffffu, v, 8);
        v += __shfl_xor_sync(0xffffffffu, v, 4);
        v += __shfl_xor_sync(0xffffffffu, v, 2);
        v += __shfl_xor_sync(0xffffffffu, v, 1);
        acc[o] = v;
    }
    if (lane == 0) {
        float noisy[8];
#pragma unroll
        for (int o = 0; o < 8; ++o) {
            float lg = acc[o] + bg[o];
            float nl = acc[8 + o] + bn[o];
            float sp = nl > 20.f ? nl : log1pf(expf(nl));
            noisy[o] = lg + noise[(long)t * 8 + o] * sp;
        }
        int i1 = 0; float v1 = noisy[0];
#pragma unroll
        for (int o = 1; o < 8; ++o) if (noisy[o] > v1) { v1 = noisy[o]; i1 = o; }
        int i2 = 0; float v2 = -3.4e38f;
#pragma unroll
        for (int o = 0; o < 8; ++o) if (o != i1 && noisy[o] > v2) { v2 = noisy[o]; i2 = o; }
        float ex = expf(v2 - v1);
        float inv = 1.f / (1.f + ex);
        int p1 = atomicAdd(&g_cnt[i1], 1);
        g_tok[i1 * NTOK + p1]  = t;
        g_gate[i1 * NTOK + p1] = inv;
        int p2 = atomicAdd(&g_cnt[i2], 1);
        g_tok[i2 * NTOK + p2]  = t;
        g_gate[i2 * NTOK + p2] = ex * inv;
    }
}

// ---------------- grouped GEMM (fp16 2-term, wmma, cp.async) ----------------
// SECOND=false: h = relu(gather(xh) @ (W1h+W1l)[e] + b1[e]) -> g_h (fp16)
// SECOND=true : out += gate * (h @ (W2h+W2l)[e] + b2[e])
template <bool SECOND>
__global__ void __launch_bounds__(256, 1)
moe_gemm_kernel(const float* __restrict__ bias, float* __restrict__ out) {
    constexpr int KDIM = SECOND ? HDIM : DDIM;
    constexpr int NDIM = SECOND ? ODIM : HDIM;
    constexpr int KT = KDIM / BK;

    int e  = blockIdx.y >> 5;
    int mt = blockIdx.y & 31;
    int cnt = g_cnt[e];
    int m0 = mt * BM;
    if (m0 >= cnt) return;
    int off = 0;
#pragma unroll
    for (int q = 0; q < NEXP; ++q) off += (q < e) ? g_cnt[q] : 0;
    int n0 = blockIdx.x * BN;
    int tid = threadIdx.x;
    int w = tid >> 5;
    int wm = (w & 1) * 64, wn = (w >> 1) * 64;

    extern __shared__ __align__(128) char raw[];
    uint32_t sbase = smem_u32(raw);

    const __half* Asrc = SECOND ? g_h : g_xh;
    const __half* Bhi  = SECOND ? g_w2h : g_w1h;
    const __half* Blo  = SECOND ? g_w2l : g_w1l;

    // A: chunk id = tid + 256*i (i<4): row = id>>3, c8 = id&7 (8 halfs = 16B)
    size_t asrc[4]; uint32_t asz[4]; uint32_t adst[4];
#pragma unroll
    for (int i = 0; i < 4; ++i) {
        int id = tid + 256 * i;
        int row = id >> 3, c8 = id & 7;
        int pos = m0 + row;
        bool aval = pos < cnt;
        asz[i] = aval ? 16u : 0u;
        if (SECOND) {
            asrc[i] = (size_t)(off + (aval ? pos : 0)) * HDIM + c8 * 8;
        } else {
            int token = aval ? g_tok[e * NTOK + pos] : 0;
            asrc[i] = (size_t)token * DDIM + c8 * 8;
        }
        adst[i] = sbase + row * (ALD * 2) + c8 * 16;
    }
    // B: chunk id = tid + 256*i (i<8): row = id>>5, c16 = id&31
    size_t bsrc[8]; uint32_t bdst[8];
#pragma unroll
    for (int i = 0; i < 8; ++i) {
        int id = tid + 256 * i;
        int row = id >> 5, c16 = id & 31;
        bsrc[i] = (size_t)e * KDIM * NDIM + (size_t)row * NDIM + n0 + c16 * 8;
        bdst[i] = sbase + OFF_BH + row * (BLD * 2) + c16 * 16;
    }

    auto fill = [&](int s, int kt) {
        int ko = kt * BK;
        uint32_t sa = s * A_STAGE, sb = s * B_STAGE;
#pragma unroll
        for (int i = 0; i < 4; ++i)
            CP_ASYNC16(adst[i] + sa, (const char*)(Asrc + asrc[i] + ko), asz[i]);
        size_t kofs = (size_t)ko * NDIM;
#pragma unroll
        for (int i = 0; i < 8; ++i) {
            CP_ASYNC16(bdst[i] + sb, (const char*)(Bhi + bsrc[i] + kofs), 16u);
            CP_ASYNC16(bdst[i] + sb + (OFF_BL - OFF_BH), (const char*)(Blo + bsrc[i] + kofs), 16u);
        }
        CP_COMMIT();
    };

    wmma::fragment<wmma::accumulator, 16, 16, 16, float> acc[4][4];
#pragma unroll
    for (int i = 0; i < 4; ++i)
#pragma unroll
        for (int j = 0; j < 4; ++j) wmma::fill_fragment(acc[i][j], 0.f);

    auto compute = [&](int s) {
        const __half* Ah = (const __half*)(raw + s * A_STAGE);
        const __half* Bh = (const __half*)(raw + OFF_BH + s * B_STAGE);
        const __half* Bl = (const __half*)(raw + OFF_BL + s * B_STAGE);
#pragma unroll
        for (int kk = 0; kk < BK; kk += 16) {
            wmma::fragment<wmma::matrix_a, 16, 16, 16, __half, wmma::row_major> fa[4];
            wmma::fragment<wmma::matrix_b, 16, 16, 16, __half, wmma::row_major> fbh[4], fbl[4];
#pragma unroll
            for (int i = 0; i < 4; ++i)
                wmma::load_matrix_sync(fa[i], Ah + (wm + 16 * i) * ALD + kk, ALD);
#pragma unroll
            for (int j = 0; j < 4; ++j) {
                wmma::load_matrix_sync(fbh[j], Bh + kk * BLD + wn + 16 * j, BLD);
                wmma::load_matrix_sync(fbl[j], Bl + kk * BLD + wn + 16 * j, BLD);
            }
#pragma unroll
            for (int i = 0; i < 4; ++i)
#pragma unroll
                for (int j = 0; j < 4; ++j) {
                    wmma::mma_sync(acc[i][j], fa[i], fbh[j], acc[i][j]);
                    wmma::mma_sync(acc[i][j], fa[i], fbl[j], acc[i][j]);
                }
        }
    };

    fill(0, 0);
    CP_WAIT0();
    __syncthreads();
#pragma unroll 1
    for (int kt = 0; kt < KT; ++kt) {
        int s = kt & 1;
        if (kt + 1 < KT) fill(s ^ 1, kt + 1);
        compute(s);
        if (kt + 1 < KT) {
            CP_WAIT0();
            __syncthreads();
        }
    }

    // epilogue via smem C tile (aliased over stage buffers)
    __syncthreads();
    float* sC = (float*)raw;
#pragma unroll
    for (int i = 0; i < 4; ++i)
#pragma unroll
        for (int j = 0; j < 4; ++j)
            wmma::store_matrix_sync(sC + (wm + 16 * i) * CLD + wn + 16 * j, acc[i][j], CLD,
                                    wmma::mem_row_major);
    __syncthreads();

    for (int q = tid; q < BM * (BN / 4); q += 256) {
        int r = q >> 6;
        int c = (q & 63) * 4;
        int pos = m0 + r;
        if (pos >= cnt) continue;
        int nb = n0 + c;
        float v0 = sC[r * CLD + c]     + bias[e * NDIM + nb];
        float v1 = sC[r * CLD + c + 1] + bias[e * NDIM + nb + 1];
        float v2 = sC[r * CLD + c + 2] + bias[e * NDIM + nb + 2];
        float v3 = sC[r * CLD + c + 3] + bias[e * NDIM + nb + 3];
        if (!SECOND) {
            v0 = fmaxf(v0, 0.f); v1 = fmaxf(v1, 0.f);
            v2 = fmaxf(v2, 0.f); v3 = fmaxf(v3, 0.f);
            size_t ob = (size_t)(off + pos) * HDIM + nb;
            __half2 p0 = __halves2half2(__float2half_rn(v0), __float2half_rn(v1));
            __half2 p1 = __halves2half2(__float2half_rn(v2), __float2half_rn(v3));
            uint2 pk;
            pk.x = *(uint32_t*)&p0; pk.y = *(uint32_t*)&p1;
            *(uint2*)(g_h + ob) = pk;
        } else {
            float gate = g_gate[e * NTOK + pos];
            int token  = g_tok[e * NTOK + pos];
            float* op = out + (size_t)token * ODIM + nb;
            atomicAdd(op,     v0 * gate);
            atomicAdd(op + 1, v1 * gate);
            atomicAdd(op + 2, v2 * gate);
            atomicAdd(op + 3, v3 * gate);
        }
    }
}

// ---------------- launch ----------------
extern "C" void kernel_launch(void* const* d_in, const int* in_sizes, int n_in,
                              void* d_out, int out_size) {
    const float* x     = (const float*)d_in[0];
    const float* noise = (const float*)d_in[1];
    const float* Wg    = (const float*)d_in[2];
    const float* bg    = (const float*)d_in[3];
    const float* Wn    = (const float*)d_in[4];
    const float* bn    = (const float*)d_in[5];
    const float* W1    = (const float*)d_in[6];
    const float* b1    = (const float*)d_in[7];
    const float* W2    = (const float*)d_in[8];
    const float* b2    = (const float*)d_in[9];
    (void)in_sizes; (void)n_in;

    void* cnt_ptr;
    cudaGetSymbolAddress(&cnt_ptr, g_cnt);

    cudaFuncSetAttribute(router_kernel, cudaFuncAttributeMaxDynamicSharedMemorySize, SMEM_ROUTER);
    cudaFuncSetAttribute(moe_gemm_kernel<false>, cudaFuncAttributeMaxDynamicSharedMemorySize, SMEM_GEMM);
    cudaFuncSetAttribute(moe_gemm_kernel<true>,  cudaFuncAttributeMaxDynamicSharedMemorySize, SMEM_GEMM);

    // launch order chosen so gemm1 is profiled launch index 5 (ncu -s 5 -c 1)
    cudaMemsetAsync(cnt_ptr, 0, NEXP * sizeof(int));                       // 0
    cudaMemsetAsync(d_out, 0, (size_t)out_size * sizeof(float));           // 1

    int n4x = NTOK * DDIM / 4;
    conv_x_kernel<<<(n4x + 255) / 256, 256>>>((const float4*)x);           // 2
    int n4w = NEXP * DDIM * HDIM / 4;
    split_w_kernel<<<(2 * n4w + 255) / 256, 256>>>((const float4*)W1,
                                                   (const float4*)W2);     // 3
    router_kernel<<<NTOK / 8, 256, SMEM_ROUTER>>>(x, noise, Wg, bg, Wn, bn); // 4

    moe_gemm_kernel<false><<<dim3(HDIM / BN, NEXP * 32), 256, SMEM_GEMM>>>(b1, nullptr);      // 5
    moe_gemm_kernel<true> <<<dim3(ODIM / BN, NEXP * 32), 256, SMEM_GEMM>>>(b2, (float*)d_out); // 6
}

// round 6
// speedup vs baseline: 4.5134x; 1.0771x over previous
#include <cuda_runtime.h>
#include <cuda_fp16.h>
#include <mma.h>
#include <math.h>
#include <cstdint>

using namespace nvcuda;

#define NTOK 4096
#define DDIM 1024
#define HDIM 4096
#define ODIM 1024
#define NEXP 8
#define NPAIR 8192

#define BM 128
#define BN 128
#define BK 64
#define ALD 72      // A smem row stride (halfs)
#define BLD 136     // B smem row stride (halfs)
#define CLD 132     // C smem row stride (floats)

#define A_STAGE 18432            // 128*72*2
#define B_STAGE 17408            // 64*136*2 (per term)
#define STG (A_STAGE + 2 * B_STAGE)   // 53248
#define OFF_BH A_STAGE
#define OFF_BL (A_STAGE + B_STAGE)
#define SMEM_GEMM (3 * STG)      // 159744 (C tile 128*132*4=67584 aliases)
#define SMEM_ROUTER (16 * DDIM * 4)

__device__ __forceinline__ uint32_t smem_u32(const void* p) {
    uint32_t a;
    asm("{ .reg .u64 t; cvta.to.shared.u64 t, %1; cvt.u32.u64 %0, t; }" : "=r"(a) : "l"(p));
    return a;
}
#define CP_ASYNC16(dst, src, sz) \
    asm volatile("cp.async.cg.shared.global [%0], [%1], 16, %2;" \
                 :: "r"(dst), "l"(src), "r"(sz))
#define CP_COMMIT() asm volatile("cp.async.commit_group;")
#define CP_WAIT0()  asm volatile("cp.async.wait_group 0;")
#define CP_WAIT1()  asm volatile("cp.async.wait_group 1;")

// ---------------- scratch (device globals) ----------------
__device__ int   g_cnt[NEXP];
__device__ int   g_tok[NEXP * NTOK];
__device__ float g_gate[NEXP * NTOK];
__device__ __half g_xh[NTOK * DDIM];                 // fp16(x)
__device__ __half g_w1h[NEXP * DDIM * HDIM];         // fp16 hi
__device__ __half g_w1l[NEXP * DDIM * HDIM];         // fp16 lo (residual)
__device__ __half g_w2h[NEXP * HDIM * ODIM];
__device__ __half g_w2l[NEXP * HDIM * ODIM];
__device__ __half g_h[(size_t)NPAIR * HDIM];         // fp16(h)

// ---------------- x: fp32 -> fp16 convert ----------------
__global__ void conv_x_kernel(const float4* __restrict__ src) {
    int i = blockIdx.x * blockDim.x + threadIdx.x;
    if (i >= NTOK * DDIM / 4) return;
    float4 v = src[i];
    __half2* dst = (__half2*)g_xh;
    dst[2 * i]     = __halves2half2(__float2half_rn(v.x), __float2half_rn(v.y));
    dst[2 * i + 1] = __halves2half2(__float2half_rn(v.z), __float2half_rn(v.w));
}

// ---------------- W1 + W2: fp32 -> fp16 hi/lo split ----------------
__global__ void split_w_kernel(const float4* __restrict__ W1,
                               const float4* __restrict__ W2) {
    const int n4 = NEXP * DDIM * HDIM / 4;
    int i = blockIdx.x * blockDim.x + threadIdx.x;
    if (i >= 2 * n4) return;
    bool second = i >= n4;
    int j = second ? i - n4 : i;
    float4 v = second ? W2[j] : W1[j];
    __half h0 = __float2half_rn(v.x);
    __half h1 = __float2half_rn(v.y);
    __half h2 = __float2half_rn(v.z);
    __half h3 = __float2half_rn(v.w);
    __half2* hi = (__half2*)(second ? g_w2h : g_w1h);
    __half2* lo = (__half2*)(second ? g_w2l : g_w1l);
    hi[2 * j]     = __halves2half2(h0, h1);
    hi[2 * j + 1] = __halves2half2(h2, h3);
    lo[2 * j]     = __halves2half2(__float2half_rn(v.x - __half2float(h0)),
                                   __float2half_rn(v.y - __half2float(h1)));
    lo[2 * j + 1] = __halves2half2(__float2half_rn(v.z - __half2float(h2)),
                                   __float2half_rn(v.w - __half2float(h3)));
}

// ---------------- router: noisy top-2 ----------------
__global__ void router_kernel(const float* __restrict__ x,
                              const float* __restrict__ noise,
                              const float* __restrict__ Wg,
                              const float* __restrict__ bg,
                              const float* __restrict__ Wn,
                              const float* __restrict__ bn) {
    extern __shared__ float Ws[];  // [16][DDIM]
    int tid = threadIdx.x;
    for (int idx = tid; idx < DDIM * NEXP; idx += blockDim.x) {
        int k = idx >> 3, o = idx & 7;
        Ws[o * DDIM + k]       = Wg[idx];
        Ws[(8 + o) * DDIM + k] = Wn[idx];
    }
    __syncthreads();
    int warp = tid >> 5, lane = tid & 31;
    int t = blockIdx.x * 8 + warp;
    float acc[16];
#pragma unroll
    for (int o = 0; o < 16; ++o) acc[o] = 0.f;
    const float* xr = x + (long)t * DDIM;
    for (int j = 0; j < 32; ++j) {
        int k = lane + 32 * j;
        float xv = xr[k];
#pragma unroll
        for (int o = 0; o < 16; ++o) acc[o] += xv * Ws[o * DDIM + k];
    }
#pragma unroll
    for (int o = 0; o < 16; ++o) {
        float v = acc[o];
        v += __shfl_xor_sync(0xffffffffu, v, 16);
        v += __shfl_xor_sync(0xffffffffu, v, 8);
        v += __shfl_xor_sync(0xffffffffu, v, 4);
        v += __shfl_xor_sync(0xffffffffu, v, 2);
        v += __shfl_xor_sync(0xffffffffu, v, 1);
        acc[o] = v;
    }
    if (lane == 0) {
        float noisy[8];
#pragma unroll
        for (int o = 0; o < 8; ++o) {
            float lg = acc[o] + bg[o];
            float nl = acc[8 + o] + bn[o];
            float sp = nl > 20.f ? nl : log1pf(expf(nl));
            noisy[o] = lg + noise[(long)t * 8 + o] * sp;
        }
        int i1 = 0; float v1 = noisy[0];
#pragma unroll
        for (int o = 1; o < 8; ++o) if (noisy[o] > v1) { v1 = noisy[o]; i1 = o; }
        int i2 = 0; float v2 = -3.4e38f;
#pragma unroll
        for (int o = 0; o < 8; ++o) if (o != i1 && noisy[o] > v2) { v2 = noisy[o]; i2 = o; }
        float ex = expf(v2 - v1);
        float inv = 1.f / (1.f + ex);
        int p1 = atomicAdd(&g_cnt[i1], 1);
        g_tok[i1 * NTOK + p1]  = t;
        g_gate[i1 * NTOK + p1] = inv;
        int p2 = atomicAdd(&g_cnt[i2], 1);
        g_tok[i2 * NTOK + p2]  = t;
        g_gate[i2 * NTOK + p2] = ex * inv;
    }
}

// ---------------- grouped GEMM (fp16 2-term, 16 warps, 3-stage cp.async) ----------------
// SECOND=false: h = relu(gather(xh) @ (W1h+W1l)[e] + b1[e]) -> g_h (fp16)
// SECOND=true : out += gate * (h @ (W2h+W2l)[e] + b2[e])
template <bool SECOND>
__global__ void __launch_bounds__(512, 1)
moe_gemm_kernel(const float* __restrict__ bias, float* __restrict__ out) {
    constexpr int KDIM = SECOND ? HDIM : DDIM;
    constexpr int NDIM = SECOND ? ODIM : HDIM;
    constexpr int KT = KDIM / BK;

    int e  = blockIdx.y >> 5;
    int mt = blockIdx.y & 31;
    int cnt = g_cnt[e];
    int m0 = mt * BM;
    if (m0 >= cnt) return;
    int off = 0;
#pragma unroll
    for (int q = 0; q < NEXP; ++q) off += (q < e) ? g_cnt[q] : 0;
    int n0 = blockIdx.x * BN;
    int tid = threadIdx.x;
    int w = tid >> 5;
    int wm = (w & 3) * 32, wn = (w >> 2) * 32;

    extern __shared__ __align__(128) char raw[];
    uint32_t sbase = smem_u32(raw);

    const __half* Asrc = SECOND ? g_h : g_xh;
    const __half* Bhi  = SECOND ? g_w2h : g_w1h;
    const __half* Blo  = SECOND ? g_w2l : g_w1l;

    // A: chunk id = tid + 512*i (i<2): row = id>>3, c8 = id&7 (8 halfs = 16B)
    size_t asrc[2]; uint32_t asz[2]; uint32_t adst[2];
#pragma unroll
    for (int i = 0; i < 2; ++i) {
        int id = tid + 512 * i;
        int row = id >> 3, c8 = id & 7;
        int pos = m0 + row;
        bool aval = pos < cnt;
        asz[i] = aval ? 16u : 0u;
        if (SECOND) {
            asrc[i] = (size_t)(off + (aval ? pos : 0)) * HDIM + c8 * 8;
        } else {
            int token = aval ? g_tok[e * NTOK + pos] : 0;
            asrc[i] = (size_t)token * DDIM + c8 * 8;
        }
        adst[i] = sbase + row * (ALD * 2) + c8 * 16;
    }
    // B: chunk id = tid + 512*i (i<2): row = id>>4, c16 = id&15
    size_t bsrc[2]; uint32_t bdst[2];
#pragma unroll
    for (int i = 0; i < 2; ++i) {
        int id = tid + 512 * i;
        int row = id >> 4, c16 = id & 15;
        bsrc[i] = (size_t)e * KDIM * NDIM + (size_t)row * NDIM + n0 + c16 * 8;
        bdst[i] = sbase + OFF_BH + row * (BLD * 2) + c16 * 16;
    }

    auto fill = [&](int s, int kt) {
        int ko = kt * BK;
        uint32_t sb = s * STG;
#pragma unroll
        for (int i = 0; i < 2; ++i)
            CP_ASYNC16(adst[i] + sb, (const char*)(Asrc + asrc[i] + ko), asz[i]);
        size_t kofs = (size_t)ko * NDIM;
#pragma unroll
        for (int i = 0; i < 2; ++i) {
            CP_ASYNC16(bdst[i] + sb, (const char*)(Bhi + bsrc[i] + kofs), 16u);
            CP_ASYNC16(bdst[i] + sb + B_STAGE, (const char*)(Blo + bsrc[i] + kofs), 16u);
        }
        CP_COMMIT();
    };

    wmma::fragment<wmma::accumulator, 16, 16, 16, float> acc[2][2];
#pragma unroll
    for (int i = 0; i < 2; ++i)
#pragma unroll
        for (int j = 0; j < 2; ++j) wmma::fill_fragment(acc[i][j], 0.f);

    auto compute = [&](int s) {
        const __half* Ah = (const __half*)(raw + s * STG);
        const __half* Bh = (const __half*)(raw + s * STG + OFF_BH);
        const __half* Bl = (const __half*)(raw + s * STG + OFF_BL);
#pragma unroll
        for (int kk = 0; kk < BK; kk += 16) {
            wmma::fragment<wmma::matrix_a, 16, 16, 16, __half, wmma::row_major> fa[2];
            wmma::fragment<wmma::matrix_b, 16, 16, 16, __half, wmma::row_major> fbh[2], fbl[2];
#pragma unroll
            for (int i = 0; i < 2; ++i)
                wmma::load_matrix_sync(fa[i], Ah + (wm + 16 * i) * ALD + kk, ALD);
#pragma unroll
            for (int j = 0; j < 2; ++j) {
                wmma::load_matrix_sync(fbh[j], Bh + kk * BLD + wn + 16 * j, BLD);
                wmma::load_matrix_sync(fbl[j], Bl + kk * BLD + wn + 16 * j, BLD);
            }
#pragma unroll
            for (int i = 0; i < 2; ++i)
#pragma unroll
                for (int j = 0; j < 2; ++j) {
                    wmma::mma_sync(acc[i][j], fa[i], fbh[j], acc[i][j]);
                    wmma::mma_sync(acc[i][j], fa[i], fbl[j], acc[i][j]);
                }
        }
    };

    fill(0, 0);
    if (KT > 1) fill(1, 1);
    int s = 0, f = 2;
#pragma unroll 1
    for (int kt = 0; kt < KT; ++kt) {
        if (kt + 1 < KT) CP_WAIT1(); else CP_WAIT0();
        __syncthreads();
        compute(s);
        if (kt + 2 < KT) fill(f, kt + 2);
        s = (s == 2) ? 0 : s + 1;
        f = (f == 2) ? 0 : f + 1;
    }

    // epilogue via smem C tile (aliased over stage buffers)
    __syncthreads();
    float* sC = (float*)raw;
#pragma unroll
    for (int i = 0; i < 2; ++i)
#pragma unroll
        for (int j = 0; j < 2; ++j)
            wmma::store_matrix_sync(sC + (wm + 16 * i) * CLD + wn + 16 * j, acc[i][j], CLD,
                                    wmma::mem_row_major);
    __syncthreads();

    if (!SECOND) {
        // write fp16 h, 8 cols per thread-chunk
        for (int q = tid; q < BM * (BN / 8); q += 512) {
            int r = q >> 4;
            int c = (q & 15) * 8;
            int pos = m0 + r;
            if (pos >= cnt) continue;
            int nb = n0 + c;
            uint4 pk;
            __half2 p[4];
#pragma unroll
            for (int u = 0; u < 4; ++u) {
                float v0 = sC[r * CLD + c + 2 * u]     + bias[e * NDIM + nb + 2 * u];
                float v1 = sC[r * CLD + c + 2 * u + 1] + bias[e * NDIM + nb + 2 * u + 1];
                p[u] = __halves2half2(__float2half_rn(fmaxf(v0, 0.f)),
                                      __float2half_rn(fmaxf(v1, 0.f)));
            }
            pk.x = *(uint32_t*)&p[0]; pk.y = *(uint32_t*)&p[1];
            pk.z = *(uint32_t*)&p[2]; pk.w = *(uint32_t*)&p[3];
            *(uint4*)(g_h + (size_t)(off + pos) * HDIM + nb) = pk;
        }
    } else {
        for (int q = tid; q < BM * (BN / 4); q += 512) {
            int r = q >> 5;
            int c = (q & 31) * 4;
            int pos = m0 + r;
            if (pos >= cnt) continue;
            float gate = g_gate[e * NTOK + pos];
            int token  = g_tok[e * NTOK + pos];
            int nb = n0 + c;
            float* op = out + (size_t)token * ODIM + nb;
#pragma unroll
            for (int u = 0; u < 4; ++u) {
                float v = sC[r * CLD + c + u] + bias[e * NDIM + nb + u];
                atomicAdd(op + u, v * gate);
            }
        }
    }
}

// ---------------- launch ----------------
extern "C" void kernel_launch(void* const* d_in, const int* in_sizes, int n_in,
                              void* d_out, int out_size) {
    const float* x     = (const float*)d_in[0];
    const float* noise = (const float*)d_in[1];
    const float* Wg    = (const float*)d_in[2];
    const float* bg    = (const float*)d_in[3];
    const float* Wn    = (const float*)d_in[4];
    const float* bn    = (const float*)d_in[5];
    const float* W1    = (const float*)d_in[6];
    const float* b1    = (const float*)d_in[7];
    const float* W2    = (const float*)d_in[8];
    const float* b2    = (const float*)d_in[9];
    (void)in_sizes; (void)n_in;

    void* cnt_ptr;
    cudaGetSymbolAddress(&cnt_ptr, g_cnt);

    cudaFuncSetAttribute(router_kernel, cudaFuncAttributeMaxDynamicSharedMemorySize, SMEM_ROUTER);
    cudaFuncSetAttribute(moe_gemm_kernel<false>, cudaFuncAttributeMaxDynamicSharedMemorySize, SMEM_GEMM);
    cudaFuncSetAttribute(moe_gemm_kernel<true>,  cudaFuncAttributeMaxDynamicSharedMemorySize, SMEM_GEMM);

    // launch order: gemm1 is profiled launch index 5 (ncu -s 5 -c 1)
    cudaMemsetAsync(cnt_ptr, 0, NEXP * sizeof(int));                       // 0
    cudaMemsetAsync(d_out, 0, (size_t)out_size * sizeof(float));           // 1

    int n4x = NTOK * DDIM / 4;
    conv_x_kernel<<<(n4x + 255) / 256, 256>>>((const float4*)x);           // 2
    int n4w = NEXP * DDIM * HDIM / 4;
    split_w_kernel<<<(2 * n4w + 255) / 256, 256>>>((const float4*)W1,
                                                   (const float4*)W2);     // 3
    router_kernel<<<NTOK / 8, 256, SMEM_ROUTER>>>(x, noise, Wg, bg, Wn, bn); // 4

    moe_gemm_kernel<false><<<dim3(HDIM / BN, NEXP * 32), 512, SMEM_GEMM>>>(b1, nullptr);      // 5
    moe_gemm_kernel<true> <<<dim3(ODIM / BN, NEXP * 32), 512, SMEM_GEMM>>>(b2, (float*)d_out); // 6
}